// round 1
// baseline (speedup 1.0000x reference)
#include <cuda_runtime.h>
#include <cuda_bf16.h>
#include <cstdint>

// Problem constants (fixed shapes for this problem)
#define NTOT 100000
#define ETOT 1600000
#define GTOT 1024
#define NB   782          // ceil(NTOT/128) GIN blocks
#define NSCAN 98          // ceil(NTOT/1024)
#define BN_EPS 1e-5f

// ---------------- device scratch (no runtime allocation allowed) ----------------
__device__ float g_bufA[NTOT * 64];       // ping
__device__ float g_bufB[NTOT * 64];       // pong
__device__ int   g_deg[NTOT];
__device__ int   g_rowptr[NTOT + 1];
__device__ int   g_cursor[NTOT];
__device__ int   g_csr[ETOT];
__device__ int   g_bsum[NSCAN];
__device__ int   g_boff[NSCAN];
__device__ float g_stats[NB * 128];       // per-block [sum(64), sumsq(64)]
__device__ float g_scale[5 * 64];         // BN folded: scale = rstd*gamma
__device__ float g_shift[5 * 64];         // shift = beta - mean*scale
__device__ float g_pooled[GTOT * 320];    // raw (pre-BN) per-graph sums
__device__ int   g_cnt[GTOT];             // nodes per graph

// ---------------- zero scratch ----------------
__global__ void zero_kernel() {
    int i0 = blockIdx.x * blockDim.x + threadIdx.x;
    int str = gridDim.x * blockDim.x;
    for (int i = i0; i < GTOT * 320; i += str) g_pooled[i] = 0.f;
    for (int i = i0; i < NTOT; i += str) g_deg[i] = 0;
    for (int i = i0; i < GTOT; i += str) g_cnt[i] = 0;
}

// ---------------- degree histogram + graph-size histogram ----------------
__global__ void hist_kernel(const int* __restrict__ dst, const int* __restrict__ batch) {
    int i = blockIdx.x * blockDim.x + threadIdx.x;
    if (i < ETOT) atomicAdd(&g_deg[dst[i]], 1);
    if (i < NTOT) atomicAdd(&g_cnt[batch[i]], 1);
}

// ---------------- 3-kernel coalesced exclusive scan of degrees ----------------
__global__ void scanA_kernel() {
    __shared__ int s[1024];
    int t = threadIdx.x;
    int i = blockIdx.x * 1024 + t;
    s[t] = (i < NTOT) ? g_deg[i] : 0;
    __syncthreads();
    for (int off = 512; off; off >>= 1) {
        if (t < off) s[t] += s[t + off];
        __syncthreads();
    }
    if (t == 0) g_bsum[blockIdx.x] = s[0];
}

__global__ void scanB_kernel() {
    int run = 0;
    for (int b = 0; b < NSCAN; b++) { g_boff[b] = run; run += g_bsum[b]; }
    g_rowptr[NTOT] = run;
}

__global__ void scanC_kernel() {
    __shared__ int s[1024];
    int t = threadIdx.x;
    int i = blockIdx.x * 1024 + t;
    int v = (i < NTOT) ? g_deg[i] : 0;
    s[t] = v;
    __syncthreads();
    for (int off = 1; off < 1024; off <<= 1) {
        int tmp = (t >= off) ? s[t - off] : 0;
        __syncthreads();
        s[t] += tmp;
        __syncthreads();
    }
    int excl = s[t] - v + g_boff[blockIdx.x];
    if (i < NTOT) { g_rowptr[i] = excl; g_cursor[i] = excl; }
}

// ---------------- edge scatter into CSR ----------------
__global__ void scatter_kernel(const int* __restrict__ src, const int* __restrict__ dst) {
    int i = blockIdx.x * blockDim.x + threadIdx.x;
    if (i < ETOT) {
        int d = dst[i];
        int p = atomicAdd(&g_cursor[d], 1);
        g_csr[p] = src[i];
    }
}

// ---------------- q = x @ W1a (11 -> 64), no bias (bias folded into layer0) ----------------
__global__ void gemm_in_kernel(const float* __restrict__ x, const float* __restrict__ W1a) {
    __shared__ float sW[11 * 64];
    __shared__ float sx[4][12];
    int t = threadIdx.x;            // 256
    int nl = t >> 6, c = t & 63;
    int node = blockIdx.x * 4 + nl;
    for (int i = t; i < 11 * 64; i += 256) sW[i] = W1a[i];
    if (t < 44) {
        int n2 = t / 11, k = t % 11;
        int nn = blockIdx.x * 4 + n2;
        sx[n2][k] = (nn < NTOT) ? x[nn * 11 + k] : 0.f;
    }
    __syncthreads();
    if (node < NTOT) {
        float a = 0.f;
#pragma unroll
        for (int k = 0; k < 11; k++) a = fmaf(sx[nl][k], sW[k * 64 + c], a);
        g_bufA[node * 64 + c] = a;
    }
}

// ---------------- fused GIN layer ----------------
// Per block: 128 nodes. Phases:
//  (1) CSR gather-sum aggregation (prev-layer BN applied analytically) -> sT
//  (2) GEMM1 (64x64) + ReLU  (skipped for FIRST: ReLU(t + b1a) done in phase 1)
//  (3) GEMM2 (64x64) + bias + ReLU
//  (4) epilogue: store raw h_pre, per-channel sum/sumsq partials, raw pooled sums (run-length atomics)
#define SMEM_FLOATS (128 * 66 + 4096 + 4096 + 64 + 64)
#define SMEM_BYTES  (SMEM_FLOATS * 4 + 128 * 4)

template <bool FIRST>
__global__ void gin_kernel(const float* __restrict__ Wa, const float* __restrict__ ba,
                           const float* __restrict__ Wb, const float* __restrict__ bb,
                           const int* __restrict__ batch, int layer) {
    const float* hin  = (layer & 1) ? g_bufB : g_bufA;
    float*       hout = (layer & 1) ? g_bufA : g_bufB;
    const float* scale_prev = g_scale + (layer - 1) * 64;
    const float* shift_prev = g_shift + (layer - 1) * 64;

    extern __shared__ float sm[];
    float* sT   = sm;                       // [128][66]
    float* sWaS = sm + 128 * 66;            // 4096
    float* sWbS = sWaS + 4096;              // 4096
    float* sBa  = sWbS + 4096;              // 64
    float* sBb  = sBa + 64;                 // 64
    int*   sBatch = (int*)(sBb + 64);       // 128
    float* sRed = sWaS;                     // alias (safe after GEMM1)

    int t = threadIdx.x;                    // 256
    int base = blockIdx.x * 128;

    if (!FIRST) {
        for (int i = t; i < 4096; i += 256) sWaS[i] = Wa[i];
    }
    for (int i = t; i < 4096; i += 256) sWbS[i] = Wb[i];
    if (t < 64) {
        if (!FIRST) sBa[t] = ba[t];
        sBb[t] = bb[t];
    }
    if (t < 128) {
        int n = base + t;
        sBatch[t] = (n < NTOT) ? batch[n] : -1;
    }

    // ---- phase 1: aggregation ----
    int warp = t >> 5, lane = t & 31;
    for (int j = 0; j < 16; j++) {
        int r = warp * 16 + j;
        int node = base + r;
        float ax = 0.f, ay = 0.f;
        if (node < NTOT) {
            float2 own = *(const float2*)(hin + node * 64 + 2 * lane);
            ax = own.x; ay = own.y;
            int s0 = g_rowptr[node], s1 = g_rowptr[node + 1];
            int e = s0;
            while (e < s1) {
                int m = s1 - e; if (m > 32) m = 32;
                int idx = (lane < m) ? g_csr[e + lane] : 0;
#pragma unroll 4
                for (int ee = 0; ee < m; ++ee) {
                    int s = __shfl_sync(0xffffffffu, idx, ee);
                    float2 v = *(const float2*)(hin + s * 64 + 2 * lane);
                    ax += v.x; ay += v.y;
                }
                e += 32;
            }
            if (FIRST) {
                float b0 = __ldg(&ba[2 * lane]), b1 = __ldg(&ba[2 * lane + 1]);
                ax = fmaxf(ax + b0, 0.f);
                ay = fmaxf(ay + b1, 0.f);
            } else {
                float kk = (float)(s1 - s0 + 1);
                float2 sc = *(const float2*)(scale_prev + 2 * lane);
                float2 sh = *(const float2*)(shift_prev + 2 * lane);
                ax = fmaf(sc.x, ax, kk * sh.x);
                ay = fmaf(sc.y, ay, kk * sh.y);
            }
        }
        sT[r * 66 + 2 * lane]     = ax;
        sT[r * 66 + 2 * lane + 1] = ay;
    }
    __syncthreads();

    int ty = t >> 4, tx = t & 15;           // 16x16 thread grid; micro-tile 8 rows x 4 cols
    float acc[8][4];

    // ---- phase 2: GEMM1 + ReLU ----
    if (!FIRST) {
#pragma unroll
        for (int i = 0; i < 8; i++)
#pragma unroll
            for (int j = 0; j < 4; j++) acc[i][j] = 0.f;
#pragma unroll 8
        for (int k = 0; k < 64; k++) {
            float4 b = *(const float4*)(sWaS + k * 64 + tx * 4);
#pragma unroll
            for (int i = 0; i < 8; i++) {
                float a = sT[(ty * 8 + i) * 66 + k];
                acc[i][0] = fmaf(a, b.x, acc[i][0]);
                acc[i][1] = fmaf(a, b.y, acc[i][1]);
                acc[i][2] = fmaf(a, b.z, acc[i][2]);
                acc[i][3] = fmaf(a, b.w, acc[i][3]);
            }
        }
        __syncthreads();
#pragma unroll
        for (int i = 0; i < 8; i++)
#pragma unroll
            for (int j = 0; j < 4; j++)
                sT[(ty * 8 + i) * 66 + tx * 4 + j] = fmaxf(acc[i][j] + sBa[tx * 4 + j], 0.f);
        __syncthreads();
    }

    // ---- phase 3: GEMM2 ----
#pragma unroll
    for (int i = 0; i < 8; i++)
#pragma unroll
        for (int j = 0; j < 4; j++) acc[i][j] = 0.f;
#pragma unroll 8
    for (int k = 0; k < 64; k++) {
        float4 b = *(const float4*)(sWbS + k * 64 + tx * 4);
#pragma unroll
        for (int i = 0; i < 8; i++) {
            float a = sT[(ty * 8 + i) * 66 + k];
            acc[i][0] = fmaf(a, b.x, acc[i][0]);
            acc[i][1] = fmaf(a, b.y, acc[i][1]);
            acc[i][2] = fmaf(a, b.z, acc[i][2]);
            acc[i][3] = fmaf(a, b.w, acc[i][3]);
        }
    }

    // ---- phase 4: epilogue ----
    float ssum[4] = {0.f, 0.f, 0.f, 0.f};
    float sqr[4]  = {0.f, 0.f, 0.f, 0.f};
    int curg = -1;
    float run[4] = {0.f, 0.f, 0.f, 0.f};
#pragma unroll
    for (int i = 0; i < 8; i++) {
        int r = ty * 8 + i;
        int node = base + r;
        if (node < NTOT) {
            float v[4];
#pragma unroll
            for (int j = 0; j < 4; j++) {
                v[j] = fmaxf(acc[i][j] + sBb[tx * 4 + j], 0.f);
                ssum[j] += v[j];
                sqr[j]  += v[j] * v[j];
            }
            float4 o = make_float4(v[0], v[1], v[2], v[3]);
            *(float4*)(hout + node * 64 + tx * 4) = o;
            int g = sBatch[r];
            if (g != curg) {
                if (curg >= 0) {
#pragma unroll
                    for (int j = 0; j < 4; j++)
                        atomicAdd(&g_pooled[curg * 320 + layer * 64 + tx * 4 + j], run[j]);
                }
                curg = g;
#pragma unroll
                for (int j = 0; j < 4; j++) run[j] = v[j];
            } else {
#pragma unroll
                for (int j = 0; j < 4; j++) run[j] += v[j];
            }
        }
    }
    if (curg >= 0) {
#pragma unroll
        for (int j = 0; j < 4; j++)
            atomicAdd(&g_pooled[curg * 320 + layer * 64 + tx * 4 + j], run[j]);
    }

    // per-channel partial stats -> sRed (aliases sWa; only GEMM1 read it, long done)
#pragma unroll
    for (int j = 0; j < 4; j++) {
        sRed[ty * 64 + tx * 4 + j]        = ssum[j];
        sRed[1024 + ty * 64 + tx * 4 + j] = sqr[j];
    }
    __syncthreads();
    if (t < 64) {
        float S = 0.f, Q = 0.f;
#pragma unroll
        for (int i2 = 0; i2 < 16; i2++) {
            S += sRed[i2 * 64 + t];
            Q += sRed[1024 + i2 * 64 + t];
        }
        g_stats[blockIdx.x * 128 + t]      = S;
        g_stats[blockIdx.x * 128 + 64 + t] = Q;
    }
}

// ---------------- BN stats finalize: mean/var -> scale/shift ----------------
__global__ void stats_kernel(const float* __restrict__ gamma_l,
                             const float* __restrict__ beta_l, int layer) {
    int c = blockIdx.x;   // 64 channels
    int t = threadIdx.x;  // 128
    __shared__ float sS[128], sQ[128];
    float S = 0.f, Q = 0.f;
    for (int b = t; b < NB; b += 128) {
        S += g_stats[b * 128 + c];
        Q += g_stats[b * 128 + 64 + c];
    }
    sS[t] = S; sQ[t] = Q;
    __syncthreads();
    for (int off = 64; off; off >>= 1) {
        if (t < off) { sS[t] += sS[t + off]; sQ[t] += sQ[t + off]; }
        __syncthreads();
    }
    if (t == 0) {
        float mean = sS[0] / (float)NTOT;
        float var  = sQ[0] / (float)NTOT - mean * mean;
        float rstd = rsqrtf(var + BN_EPS);
        float sc = rstd * gamma_l[c];
        g_scale[layer * 64 + c] = sc;
        g_shift[layer * 64 + c] = beta_l[c] - mean * sc;
    }
}

// ---------------- MLP head: BN fixup of pooled + fc1(ReLU) + fc2 ----------------
__global__ void mlp_kernel(const float* __restrict__ fc1W, const float* __restrict__ fc1b,
                           const float* __restrict__ fc2W, const float* __restrict__ fc2b,
                           float* __restrict__ out) {
    __shared__ float z[320];
    __shared__ float red[2];
    int g = blockIdx.x, t = threadIdx.x;  // 64 threads
    float cg = (float)g_cnt[g];
    for (int k = t; k < 320; k += 64)
        z[k] = fmaf(g_scale[k], g_pooled[g * 320 + k], cg * g_shift[k]);
    __syncthreads();
    float acc = fc1b[t];
    for (int k = 0; k < 320; k++)
        acc = fmaf(z[k], fc1W[k * 64 + t], acc);
    float h = fmaxf(acc, 0.f) * fc2W[t];
    for (int off = 16; off; off >>= 1) h += __shfl_down_sync(0xffffffffu, h, off);
    if ((t & 31) == 0) red[t >> 5] = h;
    __syncthreads();
    if (t == 0) out[g] = red[0] + red[1] + fc2b[0];
}

// ---------------- host launcher ----------------
extern "C" void kernel_launch(void* const* d_in, const int* in_sizes, int n_in,
                              void* d_out, int out_size) {
    const float* x     = (const float*)d_in[0];
    const int*   ei    = (const int*)d_in[1];
    const int*   batch = (const int*)d_in[2];
    const float* W1a   = (const float*)d_in[3];
    const float* b1a   = (const float*)d_in[4];
    const float* W1b   = (const float*)d_in[5];
    const float* b1b   = (const float*)d_in[6];
    const float* Wa    = (const float*)d_in[7];
    const float* ba    = (const float*)d_in[8];
    const float* Wb    = (const float*)d_in[9];
    const float* bb    = (const float*)d_in[10];
    const float* gamma = (const float*)d_in[11];
    const float* beta  = (const float*)d_in[12];
    const float* fc1W  = (const float*)d_in[13];
    const float* fc1b  = (const float*)d_in[14];
    const float* fc2W  = (const float*)d_in[15];
    const float* fc2b  = (const float*)d_in[16];
    float* out = (float*)d_out;

    const int* srcp = ei;
    const int* dstp = ei + ETOT;

    cudaFuncSetAttribute(gin_kernel<true>,  cudaFuncAttributeMaxDynamicSharedMemorySize, SMEM_BYTES);
    cudaFuncSetAttribute(gin_kernel<false>, cudaFuncAttributeMaxDynamicSharedMemorySize, SMEM_BYTES);

    zero_kernel<<<256, 256>>>();
    hist_kernel<<<(ETOT + 255) / 256, 256>>>(dstp, batch);
    scanA_kernel<<<NSCAN, 1024>>>();
    scanB_kernel<<<1, 1>>>();
    scanC_kernel<<<NSCAN, 1024>>>();
    scatter_kernel<<<(ETOT + 255) / 256, 256>>>(srcp, dstp);
    gemm_in_kernel<<<NTOT / 4, 256>>>(x, W1a);

    // layer 0 (identity GEMM1; bias b1a folded into aggregation ReLU)
    gin_kernel<true><<<NB, 256, SMEM_BYTES>>>(nullptr, b1a, W1b, b1b, batch, 0);
    stats_kernel<<<64, 128>>>(gamma, beta, 0);

    for (int l = 1; l < 5; l++) {
        gin_kernel<false><<<NB, 256, SMEM_BYTES>>>(Wa + (l - 1) * 4096, ba + (l - 1) * 64,
                                                   Wb + (l - 1) * 4096, bb + (l - 1) * 64,
                                                   batch, l);
        stats_kernel<<<64, 128>>>(gamma + l * 64, beta + l * 64, l);
    }

    mlp_kernel<<<GTOT, 64>>>(fc1W, fc1b, fc2W, fc2b, out);
}